// round 11
// baseline (speedup 1.0000x reference)
#include <cuda_runtime.h>
#include <cuda_fp16.h>

// out[b,k] = (WHT_2048(concat(x1[b],x2[b]))[k])^2 / 2048
// Two rows per thread packed as f32x2 (compute in fp32), exchanges in half2.
// Writer-indexed staging layouts -> STS.32 scatter / vector LDS gather,
// all phases bank-conflict-free. Coalesced LDG/STG.

#define THREADS 128
typedef unsigned long long u64;

__device__ __forceinline__ u64 pack2(float a, float b) {
    u64 d; asm("mov.b64 %0,{%1,%2};" : "=l"(d) : "f"(a), "f"(b)); return d;
}
__device__ __forceinline__ void unpack2(u64 v, float& a, float& b) {
    asm("mov.b64 {%0,%1},%2;" : "=f"(a), "=f"(b) : "l"(v));
}
__device__ __forceinline__ u64 add2(u64 a, u64 b) {
    u64 d; asm("add.rn.f32x2 %0,%1,%2;" : "=l"(d) : "l"(a), "l"(b)); return d;
}
__device__ __forceinline__ u64 fma2(u64 a, u64 b, u64 c) {
    u64 d; asm("fma.rn.f32x2 %0,%1,%2,%3;" : "=l"(d) : "l"(a), "l"(b), "l"(c)); return d;
}
__device__ __forceinline__ u64 mul2(u64 a, u64 b) {
    u64 d; asm("mul.rn.f32x2 %0,%1,%2;" : "=l"(d) : "l"(a), "l"(b)); return d;
}

#define BFLY(x, y) do { u64 _s = add2(x, y); (y) = fma2(y, neg1, x); (x) = _s; } while (0)

__device__ __forceinline__ void wht16(u64* v, const u64 neg1) {
#pragma unroll
    for (int m = 1; m < 16; m <<= 1)
#pragma unroll
        for (int i = 0; i < 16; ++i)
            if ((i & m) == 0) BFLY(v[i], v[i | m]);
}

__device__ __forceinline__ unsigned h2_from_v(u64 v) {
    float a, b; unpack2(v, a, b);
    __half2 h = __floats2half2_rn(a, b);
    return *reinterpret_cast<unsigned*>(&h);
}
__device__ __forceinline__ u64 v_from_h2(unsigned hbits) {
    __half2 h = *reinterpret_cast<__half2*>(&hbits);
    float2 f = __half22float2(h);
    return pack2(f.x, f.y);
}

__global__ void __launch_bounds__(THREADS) qf_wht_kernel(
    const float* __restrict__ x1,
    const float* __restrict__ x2,
    float* __restrict__ out)
{
    // two staging buffers of half2 (4B) elements; max slot = 132*15+127 = 2107
    __shared__ __align__(16) unsigned buf1[2112];
    __shared__ __align__(16) unsigned buf2[2112];

    const int t = threadIdx.x;
    const u64 neg1   = 0xBF800000BF800000ULL; // (-1.0f, -1.0f)
    const u64 scale2 = 0x3A0000003A000000ULL; // (1/2048, 1/2048)

    const int rowA = blockIdx.x * 2;
    const int rowB = rowA + 1;

    u64 v[16];

    // ---- coalesced load, layout A: v[k*4+c] = col (k*512 + 4t + c) ----
    const size_t offA1 = (size_t)rowA * 1024 + 4 * t;
    const size_t offB1 = (size_t)rowB * 1024 + 4 * t;
#pragma unroll
    for (int k = 0; k < 4; ++k) {
        const float* pa = (k < 2) ? (x1 + offA1 + (size_t)k * 512)
                                  : (x2 + offA1 + (size_t)(k - 2) * 512);
        const float* pb = (k < 2) ? (x1 + offB1 + (size_t)k * 512)
                                  : (x2 + offB1 + (size_t)(k - 2) * 512);
        float4 fa = *reinterpret_cast<const float4*>(pa);
        float4 fb = *reinterpret_cast<const float4*>(pb);
        v[k * 4 + 0] = pack2(fa.x, fb.x);
        v[k * 4 + 1] = pack2(fa.y, fb.y);
        v[k * 4 + 2] = pack2(fa.z, fb.z);
        v[k * 4 + 3] = pack2(fa.w, fb.w);
    }

    // ---- phase 1: bits 0,1 (c) and 9,10 (k) ----
    wht16(v, neg1);

    // ---- exchange 1 write: element (k,c) -> slot 132*(4k+c) + t  (STS.32) ----
#pragma unroll
    for (int w = 0; w < 16; ++w)
        buf1[132 * w + t] = h2_from_v(v[w]);
    __syncthreads();

    // ---- exchange 1 read: layout B j = 4i | (t&3) | ((t>>2)<<6)
    //      slot = 132*(4*(t>>5)+(t&3)) + 16*((t>>2)&7) + i  -> 4x LDS.128 ----
    {
        const int base1 = 132 * (4 * (t >> 5) + (t & 3)) + 16 * ((t >> 2) & 7);
#pragma unroll
        for (int u = 0; u < 4; ++u) {
            uint4 q = *reinterpret_cast<const uint4*>(&buf1[base1 + 4 * u]);
            v[4 * u + 0] = v_from_h2(q.x);
            v[4 * u + 1] = v_from_h2(q.y);
            v[4 * u + 2] = v_from_h2(q.z);
            v[4 * u + 3] = v_from_h2(q.w);
        }
    }

    // ---- phase 2: bits 2..5 ----
    wht16(v, neg1);

    // ---- exchange 2 write: element i -> slot 132*i + t  (buf2, STS.32) ----
#pragma unroll
    for (int i = 0; i < 16; ++i)
        buf2[132 * i + t] = h2_from_v(v[i]);
    __syncthreads();

    // ---- exchange 2 read: layout C j = (m&1)|((t&31)<<1)|((m>>1)<<6)|((t>>5)<<9)
    //      writer r_w = (j&3)|((j>>6)<<2), i_w = (j>>2)&15
    //      slot = 132*((t>>1)&15) + (m&1) + 2*(t&1) + 4*(m>>1) + 32*(t>>5)
    //      pairs (m even/odd) consecutive -> 8x LDS.64 ----
    {
        const int base2 = 132 * ((t >> 1) & 15) + 2 * (t & 1) + 32 * (t >> 5);
#pragma unroll
        for (int p = 0; p < 8; ++p) {
            uint2 q = *reinterpret_cast<const uint2*>(&buf2[base2 + 4 * p]);
            v[2 * p + 0] = v_from_h2(q.x);
            v[2 * p + 1] = v_from_h2(q.y);
        }
    }

    // ---- phase 3: bits 6..8 (WHT8, two copies m&1) ----
#pragma unroll
    for (int m = 1; m < 8; m <<= 1)
#pragma unroll
        for (int h = 0; h < 2; ++h)
#pragma unroll
            for (int q = 0; q < 8; ++q)
                if ((q & m) == 0) BFLY(v[q * 2 + h], v[(q | m) * 2 + h]);

    // ---- epilogue: square * 1/2048, coalesced float2 stores ----
    const int tc = ((t & 31) << 1) | ((t >> 5) << 9);
    float* oA = out + (size_t)rowA * 2048;
    float* oB = out + (size_t)rowB * 2048;
#pragma unroll
    for (int p = 0; p < 8; ++p) {
        const int j0 = tc | (p << 6);
        u64 s0 = mul2(mul2(v[2 * p],     v[2 * p]),     scale2);
        u64 s1 = mul2(mul2(v[2 * p + 1], v[2 * p + 1]), scale2);
        float a0, b0, a1, b1;
        unpack2(s0, a0, b0);
        unpack2(s1, a1, b1);
        *reinterpret_cast<float2*>(oA + j0) = make_float2(a0, a1);
        *reinterpret_cast<float2*>(oB + j0) = make_float2(b0, b1);
    }
}

extern "C" void kernel_launch(void* const* d_in, const int* in_sizes, int n_in,
                              void* d_out, int out_size)
{
    const float* x1 = (const float*)d_in[0];
    const float* x2 = (const float*)d_in[1];
    float* out = (float*)d_out;
    (void)in_sizes; (void)n_in; (void)out_size;

    qf_wht_kernel<<<4096, THREADS>>>(x1, x2, out);
}